// round 9
// baseline (speedup 1.0000x reference)
#include <cuda_runtime.h>

// DAGConstraintLayer: out = tree_min_project(sigmoid(x)) over (262144, 127) fp32.
// parent(i)=(i-1)/2, complete binary tree depth 7.
//
// sigmoid monotone => min(sig(a),sig(b)) = sig(min(a,b)): propagate min on raw x,
// sigmoid applied once per element at store time.
//
// R9 = R8 (pure register/shuffle, no smem, no barriers) + residency/stream fixes:
//  - __launch_bounds__(256, 8): <=32 regs, 64 warps/SM.
//  - grid 148*8 = 1184 blocks: 9472 warps = 100% of chip warp slots.
//  - __ldcs loads (read-once input, evict-first) and __stcs stores (write-once
//    output) keep L2 free to merge cross-row boundary sectors.
//
// Layout per warp-row: lane l holds nodes l (v0), 32+l (v1), 64+l (v2),
// 96+l (v3, lanes 0..30). Min-propagation via shuffles:
//  A) v0 levels 1..5 (5 predicated shuffle-min steps; parents finalized a step
//     earlier).  B) v1 <- v0 parents 15..31 (1 shuffle).
//  C) v2 <- parents 31..47 = v0@31 (lane 0) else v1 (2 shuffles + select).
//  D) v3 <- v1 parents 47..62 (1 shuffle).
// Two rows per loop iteration -> 8 outstanding 128B LDGs per warp.

#define NODES 127

__device__ __forceinline__ float fast_sigmoid(float v) {
    return __fdividef(1.0f, 1.0f + __expf(-v));  // MUFU.EX2 + MUFU.RCP
}

__device__ __forceinline__ void row_minprop(float& v0, float& v1, float& v2,
                                            float& v3, int lane) {
    const unsigned FULL = 0xffffffffu;
    const int plA = (lane > 0) ? ((lane - 1) >> 1) : 0;

    #pragma unroll
    for (int L = 1; L <= 5; ++L) {
        float p = __shfl_sync(FULL, v0, plA);
        const int lo = (1 << L) - 1;
        const int hi = (2 << L) - 2;
        if (lane >= lo && lane <= hi) v0 = fminf(v0, p);
    }
    v1 = fminf(v1, __shfl_sync(FULL, v0, (31 + lane) >> 1));
    {
        float pa = __shfl_sync(FULL, v1, (((63 + lane) >> 1) - 32) & 31);
        float pb = __shfl_sync(FULL, v0, 31);
        v2 = fminf(v2, (lane == 0) ? pb : pa);
    }
    v3 = fminf(v3, __shfl_sync(FULL, v1, ((95 + lane) >> 1) - 32));
}

__global__ void __launch_bounds__(256, 8)
dag_constraint_kernel(const float* __restrict__ x, float* __restrict__ out,
                      int nrows) {
    const int lane = threadIdx.x & 31;
    const int gw   = (blockIdx.x * blockDim.x + threadIdx.x) >> 5;  // global warp
    const int nw   = (gridDim.x * blockDim.x) >> 5;                 // total warps
    const bool hasv3 = (lane < 31);

    // nrows is even (262144); process row pairs.
    for (int r = gw * 2; r < nrows; r += nw * 2) {
        const float* a = x + (size_t)r * NODES;
        const float* b = a + NODES;

        // ---- 8 streaming 128B loads in flight ----
        float a0 = __ldcs(a + lane);
        float a1 = __ldcs(a + 32 + lane);
        float a2 = __ldcs(a + 64 + lane);
        float a3 = hasv3 ? __ldcs(a + 96 + lane) : 0.0f;
        float b0 = __ldcs(b + lane);
        float b1 = __ldcs(b + 32 + lane);
        float b2 = __ldcs(b + 64 + lane);
        float b3 = hasv3 ? __ldcs(b + 96 + lane) : 0.0f;

        // ---- register/shuffle min-propagation ----
        row_minprop(a0, a1, a2, a3, lane);
        row_minprop(b0, b1, b2, b3, lane);

        // ---- sigmoid + streaming stores ----
        float* oa = out + (size_t)r * NODES;
        float* ob = oa + NODES;
        __stcs(oa + lane,      fast_sigmoid(a0));
        __stcs(oa + 32 + lane, fast_sigmoid(a1));
        __stcs(oa + 64 + lane, fast_sigmoid(a2));
        if (hasv3) __stcs(oa + 96 + lane, fast_sigmoid(a3));
        __stcs(ob + lane,      fast_sigmoid(b0));
        __stcs(ob + 32 + lane, fast_sigmoid(b1));
        __stcs(ob + 64 + lane, fast_sigmoid(b2));
        if (hasv3) __stcs(ob + 96 + lane, fast_sigmoid(b3));
    }
}

extern "C" void kernel_launch(void* const* d_in, const int* in_sizes, int n_in,
                              void* d_out, int out_size) {
    const float* x = (const float*)d_in[0];
    float* out = (float*)d_out;

    const int total = in_sizes[0];      // 262144 * 127
    const int nrows = total / NODES;    // 262144 (even)

    const int grid = 148 * 8;           // 1184 blocks -> 9472 warps (full chip)
    dag_constraint_kernel<<<grid, 256>>>(x, out, nrows);
}

// round 10
// speedup vs baseline: 1.0173x; 1.0173x over previous
#include <cuda_runtime.h>

// DAGConstraintLayer: out = tree_min_project(sigmoid(x)) over (262144, 127) fp32.
// parent(i)=(i-1)/2, complete binary tree depth 7.
//
// sigmoid monotone => min(sig(a),sig(b)) = sig(min(a,b)): propagate min on raw x
// (FMNMX only), sigmoid applied once per element at store time.
//
// R10 = R3 (best proven: 2-stage cp.async ring, 32-row tiles, 7 CTAs/SM,
// block-cooperative aligned prefetch) + MUFU.TANH sigmoid:
//    sigmoid(x) = 0.5*tanh(0.5*x) + 0.5   -> FMUL + MUFU.TANH + FFMA
// (halves MUFU pressure vs EX2+RCP, shortens the P3 tail per tile).
//
// Rounds 4-9 ablations showed: barrier count, pipeline depth, occupancy beyond
// 56 warps/SM, and register/shuffle compute all leave the ~6.8 TB/s combined
// LTS/DRAM stream unchanged - R3's aligned block-cooperative stream is the
// fastest shape. Only the compute-phase length remained on the table.

#define NODES 127
#define ROWS_PER_TILE 32
#define THREADS 256
#define TILE_FLOATS (ROWS_PER_TILE * NODES)   // 4064
#define TILE_F4 (TILE_FLOATS / 4)             // 1016
#define TILE_BYTES (TILE_FLOATS * 4)          // 16256 (128B-aligned tiles)
#define SMEM_BYTES (2 * TILE_BYTES)           // 32512 -> 7 CTAs/SM @ 32 regs

__device__ __forceinline__ void cp_async16(void* smem_dst, const void* gmem_src) {
    unsigned s = (unsigned)__cvta_generic_to_shared(smem_dst);
    asm volatile("cp.async.cg.shared.global [%0], [%1], 16;\n" :: "r"(s), "l"(gmem_src));
}
__device__ __forceinline__ void cp_commit() {
    asm volatile("cp.async.commit_group;\n" ::: "memory");
}
template <int N>
__device__ __forceinline__ void cp_wait() {
    asm volatile("cp.async.wait_group %0;\n" :: "n"(N) : "memory");
}

__device__ __forceinline__ float fast_sigmoid(float v) {
    // sigmoid(v) = 0.5*tanh(0.5v) + 0.5 : FMUL + MUFU.TANH + FFMA (1 MUFU)
    float t;
    asm("tanh.approx.f32 %0, %1;" : "=f"(t) : "f"(0.5f * v));
    return fmaf(0.5f, t, 0.5f);
}

// Register-chain DFS: path-min rides in a register (no LDS-after-STS dependence).
template <int I, int REM>
__device__ __forceinline__ void dfs_min(float* __restrict__ r, float pmin) {
    float v = fminf(r[I], pmin);
    r[I] = v;
    if constexpr (REM > 0) {
        dfs_min<2 * I + 1, REM - 1>(r, v);
        dfs_min<2 * I + 2, REM - 1>(r, v);
    }
}

extern __shared__ float smem[];  // 2 tiles

__global__ void __launch_bounds__(THREADS, 7)
dag_constraint_kernel(const float* __restrict__ x, float* __restrict__ out,
                      int ntiles) {
    const int tid = threadIdx.x;
    float* buf0 = smem;
    float* buf1 = smem + TILE_FLOATS;

    const int t0 = blockIdx.x;

    // Prologue: prefetch first tile into buf0.
    if (t0 < ntiles) {
        const float4* __restrict__ src = (const float4*)(x + (size_t)t0 * TILE_FLOATS);
        float4* dst = (float4*)buf0;
        #pragma unroll
        for (int j = tid; j < TILE_F4; j += THREADS) cp_async16(dst + j, src + j);
    }
    cp_commit();

    int stage = 0;
    for (int t = t0; t < ntiles; t += gridDim.x) {
        // Prefetch next tile into the other buffer (fully consumed last iter;
        // end-of-iteration barrier guarantees it).
        const int nxt = t + gridDim.x;
        float* cur = stage ? buf1 : buf0;
        float* oth = stage ? buf0 : buf1;
        if (nxt < ntiles) {
            const float4* __restrict__ src = (const float4*)(x + (size_t)nxt * TILE_FLOATS);
            float4* dst = (float4*)oth;
            #pragma unroll
            for (int j = tid; j < TILE_F4; j += THREADS) cp_async16(dst + j, src + j);
        }
        cp_commit();
        cp_wait<1>();        // tile t complete (groups retire in order)
        __syncthreads();     // make cp.async data visible across threads

        // ---- P2: raw min-propagation; one warp per level-3 subtree ----
        {
            const int sub = tid >> 5;        // warp id 0..7 (uniform per warp)
            const int lane = tid & 31;       // row within tile
            float* r = cur + lane * NODES;   // odd stride -> bank-conflict-free

            const float v0 = r[0];                   // node 0: read-only
            const int a1 = 1 + (sub >> 2);           // node 1 or 2
            const float v1 = fminf(r[a1], v0);
            if ((sub & 3) == 0) r[a1] = v1;          // idempotent-race writes
            const int a2 = 3 + (sub >> 1);           // nodes 3..6
            const float v2 = fminf(r[a2], v1);
            if ((sub & 1) == 0) r[a2] = v2;
            switch (sub) {                           // warp-uniform
                case 0: dfs_min<7,  3>(r, v2); break;   // 15 nodes each,
                case 1: dfs_min<8,  3>(r, v2); break;   // levels 3..6
                case 2: dfs_min<9,  3>(r, v2); break;
                case 3: dfs_min<10, 3>(r, v2); break;
                case 4: dfs_min<11, 3>(r, v2); break;
                case 5: dfs_min<12, 3>(r, v2); break;
                case 6: dfs_min<13, 3>(r, v2); break;
                case 7: dfs_min<14, 3>(r, v2); break;
            }
        }
        __syncthreads();

        // ---- P3: sigmoid (tanh-based) + coalesced streaming store ----
        {
            const float4* s4 = (const float4*)cur;
            float4* __restrict__ gout = (float4*)(out + (size_t)t * TILE_FLOATS);
            #pragma unroll
            for (int j = tid; j < TILE_F4; j += THREADS) {
                float4 v = s4[j];
                v.x = fast_sigmoid(v.x);
                v.y = fast_sigmoid(v.y);
                v.z = fast_sigmoid(v.z);
                v.w = fast_sigmoid(v.w);
                __stcs(gout + j, v);
            }
        }
        __syncthreads();     // all reads of 'cur' done before it's refilled
        stage ^= 1;
    }
}

extern "C" void kernel_launch(void* const* d_in, const int* in_sizes, int n_in,
                              void* d_out, int out_size) {
    const float* x = (const float*)d_in[0];
    float* out = (float*)d_out;

    const int total = in_sizes[0];              // 262144 * 127
    const int rows = total / NODES;             // 262144
    const int ntiles = rows / ROWS_PER_TILE;    // 8192

    int grid = 148 * 7;                         // persistent: 7 CTAs/SM
    if (grid > ntiles) grid = ntiles;

    dag_constraint_kernel<<<grid, THREADS, SMEM_BYTES>>>(x, out, ntiles);
}